// round 1
// baseline (speedup 1.0000x reference)
#include <cuda_runtime.h>
#include <cstdio>

#define NPTS 65536
#define HID  256
#define SLICE ((size_t)NPTS * HID)   // elements per channel
#define NCH  13

// channel order: h, x, y, t, xx, xy, yy, xt, yt, xxx, xxy, xyy, yyy
// Two ping-pong activation buffers, 13 channels each.
static __device__ float g_bufA[(size_t)NCH * NPTS * HID];
static __device__ float g_bufB[(size_t)NCH * NPTS * HID];

// ---------------------------------------------------------------------------
// Layer 1: z1 = W1 q + b1. Input tangents are columns of W1 (constant),
// second/third pre-activation derivatives are zero.
// ---------------------------------------------------------------------------
__global__ void layer1_kernel(const float* __restrict__ x,
                              const float* __restrict__ y,
                              const float* __restrict__ t,
                              const float* __restrict__ W1,
                              const float* __restrict__ b1,
                              float* __restrict__ A) {
    int e = blockIdx.x * blockDim.x + threadIdx.x;
    if (e >= NPTS * HID) return;
    int n = e >> 8;
    int k = e & 255;
    float cx = W1[k * 3 + 0];
    float cy = W1[k * 3 + 1];
    float ct = W1[k * 3 + 2];
    float z = cx * x[n] + cy * y[n] + ct * t[n] + b1[k];
    float h = tanhf(z);
    float d = 1.0f - h * h;
    const size_t S = SLICE;
    A[e] = h;
    A[S * 1 + e] = d * cx;
    A[S * 2 + e] = d * cy;
    A[S * 3 + e] = d * ct;
    float m2 = -2.0f * h * d;
    A[S * 4 + e] = m2 * cx * cx;
    A[S * 5 + e] = m2 * cx * cy;
    A[S * 6 + e] = m2 * cy * cy;
    A[S * 7 + e] = m2 * cx * ct;
    A[S * 8 + e] = m2 * cy * ct;
    float m3 = d * (6.0f * h * h - 2.0f);
    A[S * 9 + e]  = m3 * cx * cx * cx;
    A[S * 10 + e] = m3 * cx * cx * cy;
    A[S * 11 + e] = m3 * cx * cy * cy;
    A[S * 12 + e] = m3 * cy * cy * cy;
}

// ---------------------------------------------------------------------------
// GEMM (NT): C[m, j] = sum_k A[m, k] * W[j, k]   (K = N = 256 fixed)
// 64x64 tile, BK=16, 256 threads, 4x4 per thread, float4 I/O.
// M is encoded in gridDim.x (M/64 tiles), so all dims are exact multiples.
// ---------------------------------------------------------------------------
__global__ void gemm64(const float* __restrict__ A,
                       const float* __restrict__ W,
                       float* __restrict__ C) {
    __shared__ float As[16][64];
    __shared__ float Ws[16][64];
    const int tid = threadIdx.x;
    const int tx = tid & 15;
    const int ty = tid >> 4;
    const int lr = tid >> 2;         // 0..63
    const int lc = (tid & 3) << 2;   // 0,4,8,12
    const size_t arow = (size_t)(blockIdx.x * 64 + lr) * 256;
    const size_t wrow = (size_t)(blockIdx.y * 64 + lr) * 256;

    float acc[4][4];
#pragma unroll
    for (int i = 0; i < 4; i++)
#pragma unroll
        for (int j = 0; j < 4; j++) acc[i][j] = 0.0f;

    for (int k0 = 0; k0 < 256; k0 += 16) {
        float4 a4 = *(const float4*)(A + arow + k0 + lc);
        float4 w4 = *(const float4*)(W + wrow + k0 + lc);
        __syncthreads();
        As[lc + 0][lr] = a4.x; As[lc + 1][lr] = a4.y;
        As[lc + 2][lr] = a4.z; As[lc + 3][lr] = a4.w;
        Ws[lc + 0][lr] = w4.x; Ws[lc + 1][lr] = w4.y;
        Ws[lc + 2][lr] = w4.z; Ws[lc + 3][lr] = w4.w;
        __syncthreads();
#pragma unroll
        for (int kk = 0; kk < 16; kk++) {
            float4 ra = *(const float4*)&As[kk][ty << 2];
            float4 rb = *(const float4*)&Ws[kk][tx << 2];
            float av[4] = {ra.x, ra.y, ra.z, ra.w};
            float bv[4] = {rb.x, rb.y, rb.z, rb.w};
#pragma unroll
            for (int i = 0; i < 4; i++)
#pragma unroll
                for (int j = 0; j < 4; j++) acc[i][j] += av[i] * bv[j];
        }
    }

    const int cm = blockIdx.x * 64 + (ty << 2);
    const int cn = blockIdx.y * 64 + (tx << 2);
#pragma unroll
    for (int i = 0; i < 4; i++) {
        float4 o = make_float4(acc[i][0], acc[i][1], acc[i][2], acc[i][3]);
        *(float4*)(C + (size_t)(cm + i) * 256 + cn) = o;
    }
}

// ---------------------------------------------------------------------------
// Pointwise jet propagation through tanh for a full 13-channel layer.
// In-place on Z (Z becomes the next layer's activations A).
// ---------------------------------------------------------------------------
__global__ void combine_kernel(float* __restrict__ Z, const float* __restrict__ b) {
    int e = blockIdx.x * blockDim.x + threadIdx.x;
    if (e >= NPTS * HID) return;
    int k = e & 255;
    const size_t S = SLICE;
    float zh = Z[e] + b[k];
    float zx = Z[S + e], zy = Z[2 * S + e], zt = Z[3 * S + e];
    float zxx = Z[4 * S + e], zxy = Z[5 * S + e], zyy = Z[6 * S + e];
    float zxt = Z[7 * S + e], zyt = Z[8 * S + e];
    float zxxx = Z[9 * S + e], zxxy = Z[10 * S + e];
    float zxyy = Z[11 * S + e], zyyy = Z[12 * S + e];

    float h = tanhf(zh);
    float d = 1.0f - h * h;
    float hd2 = -2.0f * h * d;
    float c3 = (4.0f * h * h - 2.0f * d) * d;

    Z[e] = h;
    Z[S + e] = d * zx;
    Z[2 * S + e] = d * zy;
    Z[3 * S + e] = d * zt;
    Z[4 * S + e] = d * zxx + hd2 * zx * zx;
    Z[5 * S + e] = d * zxy + hd2 * zx * zy;
    Z[6 * S + e] = d * zyy + hd2 * zy * zy;
    Z[7 * S + e] = d * zxt + hd2 * zx * zt;
    Z[8 * S + e] = d * zyt + hd2 * zy * zt;
    Z[9 * S + e]  = d * zxxx + hd2 * 3.0f * zx * zxx + c3 * zx * zx * zx;
    Z[10 * S + e] = d * zxxy + hd2 * (zy * zxx + 2.0f * zx * zxy) + c3 * zx * zx * zy;
    Z[11 * S + e] = d * zxyy + hd2 * (2.0f * zy * zxy + zx * zyy) + c3 * zx * zy * zy;
    Z[12 * S + e] = d * zyyy + hd2 * 3.0f * zy * zyy + c3 * zy * zy * zy;
}

// ---------------------------------------------------------------------------
// Data head: hd = tanh(Zd0 + bd1); p_pred = Wd2[1]·hd + bd2[1];
// u_pred = Wd2[0]·(d⊙Zd_y); v_pred = -Wd2[0]·(d⊙Zd_x). One warp per sample.
// ---------------------------------------------------------------------------
__global__ void data_reduce(const float* __restrict__ Zd,
                            const float* __restrict__ bd1,
                            const float* __restrict__ Wd2,
                            const float* __restrict__ bd2,
                            float* __restrict__ out) {
    int warp = (blockIdx.x * blockDim.x + threadIdx.x) >> 5;
    int lane = threadIdx.x & 31;
    if (warp >= NPTS) return;
    const size_t S = SLICE;
    const size_t base = (size_t)warp * 256;
    float ap = 0.0f, au = 0.0f, av = 0.0f;
#pragma unroll
    for (int kk = lane; kk < 256; kk += 32) {
        size_t e = base + kk;
        float zh = Zd[e] + bd1[kk];
        float h = tanhf(zh);
        float d = 1.0f - h * h;
        float hx = d * Zd[S + e];
        float hy = d * Zd[2 * S + e];
        float w0 = Wd2[kk];
        float w1 = Wd2[256 + kk];
        ap += w1 * h;
        au += w0 * hy;
        av += w0 * hx;
    }
#pragma unroll
    for (int o = 16; o; o >>= 1) {
        ap += __shfl_xor_sync(0xffffffffu, ap, o);
        au += __shfl_xor_sync(0xffffffffu, au, o);
        av += __shfl_xor_sync(0xffffffffu, av, o);
    }
    if (lane == 0) {
        out[warp] = ap + bd2[1];
        out[NPTS + warp] = au;
        out[2 * NPTS + warp] = -av;
    }
}

// ---------------------------------------------------------------------------
// PDE head: apply tanh jet rules inline, contract all 12 derivative channels
// with Wp2 row 0 (streamfunction) and first-order channels with row 1
// (pressure), then assemble the Navier-Stokes residuals f, g.
// One warp per sample.
// ---------------------------------------------------------------------------
__global__ void pde_reduce(const float* __restrict__ Z,
                           const float* __restrict__ bp1,
                           const float* __restrict__ Wp2,
                           const float* __restrict__ lam1p,
                           const float* __restrict__ lam2p,
                           float* __restrict__ out) {
    int warp = (blockIdx.x * blockDim.x + threadIdx.x) >> 5;
    int lane = threadIdx.x & 31;
    if (warp >= NPTS) return;
    const size_t S = SLICE;
    const size_t base = (size_t)warp * 256;

    float acc[14];
#pragma unroll
    for (int i = 0; i < 14; i++) acc[i] = 0.0f;

#pragma unroll
    for (int kk = lane; kk < 256; kk += 32) {
        size_t e = base + kk;
        float zh = Z[e] + bp1[kk];
        float h = tanhf(zh);
        float d = 1.0f - h * h;
        float zx = Z[S + e], zy = Z[2 * S + e], zt = Z[3 * S + e];
        float zxx = Z[4 * S + e], zxy = Z[5 * S + e], zyy = Z[6 * S + e];
        float zxt = Z[7 * S + e], zyt = Z[8 * S + e];
        float zxxx = Z[9 * S + e], zxxy = Z[10 * S + e];
        float zxyy = Z[11 * S + e], zyyy = Z[12 * S + e];
        float hd2 = -2.0f * h * d;
        float c3 = (4.0f * h * h - 2.0f * d) * d;

        float hx = d * zx, hy = d * zy, ht = d * zt;
        float hxx = d * zxx + hd2 * zx * zx;
        float hxy = d * zxy + hd2 * zx * zy;
        float hyy = d * zyy + hd2 * zy * zy;
        float hxt = d * zxt + hd2 * zx * zt;
        float hyt = d * zyt + hd2 * zy * zt;
        float hxxx = d * zxxx + hd2 * 3.0f * zx * zxx + c3 * zx * zx * zx;
        float hxxy = d * zxxy + hd2 * (zy * zxx + 2.0f * zx * zxy) + c3 * zx * zx * zy;
        float hxyy = d * zxyy + hd2 * (2.0f * zy * zxy + zx * zyy) + c3 * zx * zy * zy;
        float hyyy = d * zyyy + hd2 * 3.0f * zy * zyy + c3 * zy * zy * zy;

        float w0 = Wp2[kk];
        float w1 = Wp2[256 + kk];
        acc[0] += w0 * hx;   acc[1] += w0 * hy;   acc[2] += w0 * ht;
        acc[3] += w0 * hxx;  acc[4] += w0 * hxy;  acc[5] += w0 * hyy;
        acc[6] += w0 * hxt;  acc[7] += w0 * hyt;
        acc[8] += w0 * hxxx; acc[9] += w0 * hxxy;
        acc[10] += w0 * hxyy; acc[11] += w0 * hyyy;
        acc[12] += w1 * hx;  acc[13] += w1 * hy;
    }
#pragma unroll
    for (int i = 0; i < 14; i++)
#pragma unroll
        for (int o = 16; o; o >>= 1) acc[i] += __shfl_xor_sync(0xffffffffu, acc[i], o);

    if (lane == 0) {
        float lam1 = lam1p[0], lam2 = lam2p[0];
        float sx = acc[0], sy = acc[1];
        float sxx = acc[3], sxy = acc[4], syy = acc[5], sxt = acc[6], syt = acc[7];
        float sxxx = acc[8], sxxy = acc[9], sxyy = acc[10], syyy = acc[11];
        float px = acc[12], py = acc[13];
        float u = sy, v = -sx;
        // u = s_y, v = -s_x; u_x = s_xy, u_y = s_yy, u_t = s_yt
        // v_x = -s_xx, v_y = -s_xy, v_t = -s_xt
        // u_xx = s_xxy, u_yy = s_yyy, v_xx = -s_xxx, v_yy = -s_xyy
        float f = lam1 * (syt + u * sxy + v * syy) + px - lam2 * (sxxy + syyy);
        float g = lam1 * (-sxt + u * (-sxx) + v * (-sxy)) + py - lam2 * (-sxxx - sxyy);
        out[3 * NPTS + warp] = f;
        out[4 * NPTS + warp] = g;
    }
}

// ---------------------------------------------------------------------------
// Host launch
// ---------------------------------------------------------------------------
extern "C" void kernel_launch(void* const* d_in, const int* in_sizes, int n_in,
                              void* d_out, int out_size) {
    const float* x   = (const float*)d_in[0];
    const float* y   = (const float*)d_in[1];
    const float* t   = (const float*)d_in[2];
    // d_in[3..5] = p, u, v (data targets; unused by the outputs)
    const float* W1  = (const float*)d_in[6];
    const float* b1  = (const float*)d_in[7];
    const float* W2  = (const float*)d_in[8];
    const float* b2  = (const float*)d_in[9];
    const float* W3  = (const float*)d_in[10];
    const float* b3  = (const float*)d_in[11];
    const float* Wp1 = (const float*)d_in[12];
    const float* bp1 = (const float*)d_in[13];
    const float* Wp2 = (const float*)d_in[14];
    // d_in[15] = bp2 (does not affect any output)
    const float* Wd1 = (const float*)d_in[16];
    const float* bd1 = (const float*)d_in[17];
    const float* Wd2 = (const float*)d_in[18];
    const float* bd2 = (const float*)d_in[19];
    const float* lam1 = (const float*)d_in[20];
    const float* lam2 = (const float*)d_in[21];
    float* out = (float*)d_out;

    float *A = nullptr, *B = nullptr;
    cudaGetSymbolAddress((void**)&A, g_bufA);
    cudaGetSymbolAddress((void**)&B, g_bufB);

    const int NH = NPTS * HID;               // 16,777,216
    const int M13_TILES = NCH * NPTS / 64;   // 13312
    const int M3_TILES = 3 * NPTS / 64;      // 3072

    // Layer 1 + jet seed
    layer1_kernel<<<NH / 256, 256>>>(x, y, t, W1, b1, A);

    // Layer 2
    gemm64<<<dim3(M13_TILES, 4), 256>>>(A, W2, B);
    combine_kernel<<<NH / 256, 256>>>(B, b2);

    // Layer 3
    gemm64<<<dim3(M13_TILES, 4), 256>>>(B, W3, A);
    combine_kernel<<<NH / 256, 256>>>(A, b3);

    // Data head (channels 0..2 of A are the first 3*N rows)
    gemm64<<<dim3(M3_TILES, 4), 256>>>(A, Wd1, B);
    data_reduce<<<NPTS / 8, 256>>>(B, bd1, Wd2, bd2, out);

    // PDE head (all 13 channels)
    gemm64<<<dim3(M13_TILES, 4), 256>>>(A, Wp1, B);
    pde_reduce<<<NPTS / 8, 256>>>(B, bp1, Wp2, lam1, lam2, out);
}

// round 2
// speedup vs baseline: 2.1474x; 2.1474x over previous
#include <cuda_runtime.h>
#include <cuda_bf16.h>

#define NPTS 65536
#define HID  256
#define SLICE ((size_t)NPTS * HID)   // elements per channel
#define NCH  13

// channel order: h, x, y, t, xx, xy, yy, xt, yt, xxx, xxy, xyy, yyy
static __device__ float g_bufA[(size_t)NCH * NPTS * HID];
static __device__ float g_bufB[(size_t)NCH * NPTS * HID];

// ---------------------------------------------------------------------------
// Layer 1: z1 = W1 q + b1, seed the 13-channel tanh jet.
// ---------------------------------------------------------------------------
__global__ void layer1_kernel(const float* __restrict__ x,
                              const float* __restrict__ y,
                              const float* __restrict__ t,
                              const float* __restrict__ W1,
                              const float* __restrict__ b1,
                              float* __restrict__ A) {
    int e = blockIdx.x * blockDim.x + threadIdx.x;
    if (e >= NPTS * HID) return;
    int n = e >> 8;
    int k = e & 255;
    float cx = W1[k * 3 + 0];
    float cy = W1[k * 3 + 1];
    float ct = W1[k * 3 + 2];
    float z = cx * x[n] + cy * y[n] + ct * t[n] + b1[k];
    float h = tanhf(z);
    float d = 1.0f - h * h;
    const size_t S = SLICE;
    A[e] = h;
    A[S * 1 + e] = d * cx;
    A[S * 2 + e] = d * cy;
    A[S * 3 + e] = d * ct;
    float m2 = -2.0f * h * d;
    A[S * 4 + e] = m2 * cx * cx;
    A[S * 5 + e] = m2 * cx * cy;
    A[S * 6 + e] = m2 * cy * cy;
    A[S * 7 + e] = m2 * cx * ct;
    A[S * 8 + e] = m2 * cy * ct;
    float m3 = d * (6.0f * h * h - 2.0f);
    A[S * 9 + e]  = m3 * cx * cx * cx;
    A[S * 10 + e] = m3 * cx * cx * cy;
    A[S * 11 + e] = m3 * cx * cy * cy;
    A[S * 12 + e] = m3 * cy * cy * cy;
}

// ---------------------------------------------------------------------------
// bf16 split-2 tensor-core GEMM (NT): C[m,n] = sum_k A[m,k] * W[n,k], K=N=256.
// Block tile 128x128, 8 warps (warp tile 32x64), k-chunk 16.
// Split each fp32 into bf16 hi (truncation) + bf16 lo (residual);
// C = Ah*Bh + Ah*Bl + Al*Bh  (fp32 accumulate; lo*lo dropped ~2^-16).
// ---------------------------------------------------------------------------
__device__ __forceinline__ void mma_bf16(float* c, const unsigned* a,
                                         unsigned b0, unsigned b1) {
    asm volatile(
        "mma.sync.aligned.m16n8k16.row.col.f32.bf16.bf16.f32 "
        "{%0,%1,%2,%3}, {%4,%5,%6,%7}, {%8,%9}, {%0,%1,%2,%3};"
        : "+f"(c[0]), "+f"(c[1]), "+f"(c[2]), "+f"(c[3])
        : "r"(a[0]), "r"(a[1]), "r"(a[2]), "r"(a[3]), "r"(b0), "r"(b1));
}

// split a pair of floats into packed bf16x2 hi (truncate) and lo (residual, RN)
__device__ __forceinline__ void split2(float f0, float f1,
                                       unsigned& hi, unsigned& lo) {
    unsigned u0 = __float_as_uint(f0);
    unsigned u1 = __float_as_uint(f1);
    hi = __byte_perm(u0, u1, 0x7632);           // {f1.top16, f0.top16}
    float h0 = __uint_as_float(u0 & 0xFFFF0000u);
    float h1 = __uint_as_float(u1 & 0xFFFF0000u);
    float r0 = f0 - h0;
    float r1 = f1 - h1;
    asm("cvt.rn.bf16x2.f32 %0, %1, %2;" : "=r"(lo) : "f"(r1), "f"(r0));
}

#define SPAD 12   // padded row stride in uint32 (8 data + 4 pad): conflict-free

__global__ void __launch_bounds__(256)
gemm_bf16(const float* __restrict__ A,
          const float* __restrict__ W,
          float* __restrict__ C) {
    __shared__ unsigned AsHi[128 * SPAD], AsLo[128 * SPAD];
    __shared__ unsigned WsHi[128 * SPAD], WsLo[128 * SPAD];

    const int tid  = threadIdx.x;
    const int lane = tid & 31;
    const int warp = tid >> 5;
    const int g    = lane >> 2;       // group 0..7
    const int t4   = lane & 3;        // 0..3
    const int wm   = (warp & 3) * 32; // warp M offset in tile
    const int wn   = (warp >> 2) * 64;

    const size_t blockRow = (size_t)blockIdx.x * 128;
    const int    blockN   = blockIdx.y * 128;

    // staging assignment: row = tid/2, col-group = (tid&1)*8 floats
    const int ldRow = tid >> 1;
    const int ldCg  = (tid & 1) * 8;
    const float* Ag = A + (blockRow + ldRow) * 256 + ldCg;
    const float* Wg = W + (size_t)(blockN + ldRow) * 256 + ldCg;

    float acc[2][8][4];
#pragma unroll
    for (int i = 0; i < 2; i++)
#pragma unroll
        for (int j = 0; j < 8; j++)
#pragma unroll
            for (int l = 0; l < 4; l++) acc[i][j][l] = 0.0f;

    float4 pa0, pa1, pw0, pw1;

    // prologue: load chunk 0
    pa0 = *(const float4*)(Ag);
    pa1 = *(const float4*)(Ag + 4);
    pw0 = *(const float4*)(Wg);
    pw1 = *(const float4*)(Wg + 4);

    const int sbase = ldRow * SPAD + (ldCg >> 1);

#pragma unroll 1
    for (int kc = 0; kc < 16; kc++) {
        // store staged regs -> smem (converted)
        {
            unsigned h, l;
            split2(pa0.x, pa0.y, h, l); AsHi[sbase + 0] = h; AsLo[sbase + 0] = l;
            split2(pa0.z, pa0.w, h, l); AsHi[sbase + 1] = h; AsLo[sbase + 1] = l;
            split2(pa1.x, pa1.y, h, l); AsHi[sbase + 2] = h; AsLo[sbase + 2] = l;
            split2(pa1.z, pa1.w, h, l); AsHi[sbase + 3] = h; AsLo[sbase + 3] = l;
            split2(pw0.x, pw0.y, h, l); WsHi[sbase + 0] = h; WsLo[sbase + 0] = l;
            split2(pw0.z, pw0.w, h, l); WsHi[sbase + 1] = h; WsLo[sbase + 1] = l;
            split2(pw1.x, pw1.y, h, l); WsHi[sbase + 2] = h; WsLo[sbase + 2] = l;
            split2(pw1.z, pw1.w, h, l); WsHi[sbase + 3] = h; WsLo[sbase + 3] = l;
        }
        __syncthreads();

        // prefetch next chunk
        if (kc < 15) {
            int ko = (kc + 1) * 16;
            pa0 = *(const float4*)(Ag + ko);
            pa1 = *(const float4*)(Ag + ko + 4);
            pw0 = *(const float4*)(Wg + ko);
            pw1 = *(const float4*)(Wg + ko + 4);
        }

        // load A fragments (2 m-tiles)
        unsigned aH[2][4], aL[2][4];
#pragma unroll
        for (int mt = 0; mt < 2; mt++) {
            int r0 = (wm + mt * 16 + g) * SPAD;
            aH[mt][0] = AsHi[r0 + t4];
            aH[mt][1] = AsHi[r0 + 8 * SPAD + t4];
            aH[mt][2] = AsHi[r0 + t4 + 4];
            aH[mt][3] = AsHi[r0 + 8 * SPAD + t4 + 4];
            aL[mt][0] = AsLo[r0 + t4];
            aL[mt][1] = AsLo[r0 + 8 * SPAD + t4];
            aL[mt][2] = AsLo[r0 + t4 + 4];
            aL[mt][3] = AsLo[r0 + 8 * SPAD + t4 + 4];
        }

#pragma unroll
        for (int nt = 0; nt < 8; nt++) {
            int n0 = (wn + nt * 8 + g) * SPAD;
            unsigned bH0 = WsHi[n0 + t4];
            unsigned bH1 = WsHi[n0 + t4 + 4];
            unsigned bL0 = WsLo[n0 + t4];
            unsigned bL1 = WsLo[n0 + t4 + 4];
#pragma unroll
            for (int mt = 0; mt < 2; mt++) {
                mma_bf16(acc[mt][nt], aH[mt], bH0, bH1);
                mma_bf16(acc[mt][nt], aH[mt], bL0, bL1);
                mma_bf16(acc[mt][nt], aL[mt], bH0, bH1);
            }
        }
        __syncthreads();
    }

    // epilogue
#pragma unroll
    for (int mt = 0; mt < 2; mt++) {
        size_t row = blockRow + wm + mt * 16 + g;
#pragma unroll
        for (int nt = 0; nt < 8; nt++) {
            int col = blockN + wn + nt * 8 + t4 * 2;
            float2 v0 = make_float2(acc[mt][nt][0], acc[mt][nt][1]);
            float2 v1 = make_float2(acc[mt][nt][2], acc[mt][nt][3]);
            *(float2*)(C + row * 256 + col) = v0;
            *(float2*)(C + (row + 8) * 256 + col) = v1;
        }
    }
}

// ---------------------------------------------------------------------------
// Pointwise jet propagation through tanh for a full 13-channel layer (in-place)
// ---------------------------------------------------------------------------
__global__ void combine_kernel(float* __restrict__ Z, const float* __restrict__ b) {
    int e = blockIdx.x * blockDim.x + threadIdx.x;
    if (e >= NPTS * HID) return;
    int k = e & 255;
    const size_t S = SLICE;
    float zh = Z[e] + b[k];
    float zx = Z[S + e], zy = Z[2 * S + e], zt = Z[3 * S + e];
    float zxx = Z[4 * S + e], zxy = Z[5 * S + e], zyy = Z[6 * S + e];
    float zxt = Z[7 * S + e], zyt = Z[8 * S + e];
    float zxxx = Z[9 * S + e], zxxy = Z[10 * S + e];
    float zxyy = Z[11 * S + e], zyyy = Z[12 * S + e];

    float h = tanhf(zh);
    float d = 1.0f - h * h;
    float hd2 = -2.0f * h * d;
    float c3 = (4.0f * h * h - 2.0f * d) * d;

    Z[e] = h;
    Z[S + e] = d * zx;
    Z[2 * S + e] = d * zy;
    Z[3 * S + e] = d * zt;
    Z[4 * S + e] = d * zxx + hd2 * zx * zx;
    Z[5 * S + e] = d * zxy + hd2 * zx * zy;
    Z[6 * S + e] = d * zyy + hd2 * zy * zy;
    Z[7 * S + e] = d * zxt + hd2 * zx * zt;
    Z[8 * S + e] = d * zyt + hd2 * zy * zt;
    Z[9 * S + e]  = d * zxxx + hd2 * 3.0f * zx * zxx + c3 * zx * zx * zx;
    Z[10 * S + e] = d * zxxy + hd2 * (zy * zxx + 2.0f * zx * zxy) + c3 * zx * zx * zy;
    Z[11 * S + e] = d * zxyy + hd2 * (2.0f * zy * zxy + zx * zyy) + c3 * zx * zy * zy;
    Z[12 * S + e] = d * zyyy + hd2 * 3.0f * zy * zyy + c3 * zy * zy * zy;
}

// ---------------------------------------------------------------------------
// Data head reduction: one warp per sample.
// ---------------------------------------------------------------------------
__global__ void data_reduce(const float* __restrict__ Zd,
                            const float* __restrict__ bd1,
                            const float* __restrict__ Wd2,
                            const float* __restrict__ bd2,
                            float* __restrict__ out) {
    int warp = (blockIdx.x * blockDim.x + threadIdx.x) >> 5;
    int lane = threadIdx.x & 31;
    if (warp >= NPTS) return;
    const size_t S = SLICE;
    const size_t base = (size_t)warp * 256;
    float ap = 0.0f, au = 0.0f, av = 0.0f;
#pragma unroll
    for (int kk = lane; kk < 256; kk += 32) {
        size_t e = base + kk;
        float zh = Zd[e] + bd1[kk];
        float h = tanhf(zh);
        float d = 1.0f - h * h;
        float hx = d * Zd[S + e];
        float hy = d * Zd[2 * S + e];
        float w0 = Wd2[kk];
        float w1 = Wd2[256 + kk];
        ap += w1 * h;
        au += w0 * hy;
        av += w0 * hx;
    }
#pragma unroll
    for (int o = 16; o; o >>= 1) {
        ap += __shfl_xor_sync(0xffffffffu, ap, o);
        au += __shfl_xor_sync(0xffffffffu, au, o);
        av += __shfl_xor_sync(0xffffffffu, av, o);
    }
    if (lane == 0) {
        out[warp] = ap + bd2[1];
        out[NPTS + warp] = au;
        out[2 * NPTS + warp] = -av;
    }
}

// ---------------------------------------------------------------------------
// PDE head reduction: tanh jet + Wp2 contraction + NS residuals. One warp/sample.
// ---------------------------------------------------------------------------
__global__ void pde_reduce(const float* __restrict__ Z,
                           const float* __restrict__ bp1,
                           const float* __restrict__ Wp2,
                           const float* __restrict__ lam1p,
                           const float* __restrict__ lam2p,
                           float* __restrict__ out) {
    int warp = (blockIdx.x * blockDim.x + threadIdx.x) >> 5;
    int lane = threadIdx.x & 31;
    if (warp >= NPTS) return;
    const size_t S = SLICE;
    const size_t base = (size_t)warp * 256;

    float acc[14];
#pragma unroll
    for (int i = 0; i < 14; i++) acc[i] = 0.0f;

#pragma unroll
    for (int kk = lane; kk < 256; kk += 32) {
        size_t e = base + kk;
        float zh = Z[e] + bp1[kk];
        float h = tanhf(zh);
        float d = 1.0f - h * h;
        float zx = Z[S + e], zy = Z[2 * S + e], zt = Z[3 * S + e];
        float zxx = Z[4 * S + e], zxy = Z[5 * S + e], zyy = Z[6 * S + e];
        float zxt = Z[7 * S + e], zyt = Z[8 * S + e];
        float zxxx = Z[9 * S + e], zxxy = Z[10 * S + e];
        float zxyy = Z[11 * S + e], zyyy = Z[12 * S + e];
        float hd2 = -2.0f * h * d;
        float c3 = (4.0f * h * h - 2.0f * d) * d;

        float hx = d * zx, hy = d * zy, ht = d * zt;
        float hxx = d * zxx + hd2 * zx * zx;
        float hxy = d * zxy + hd2 * zx * zy;
        float hyy = d * zyy + hd2 * zy * zy;
        float hxt = d * zxt + hd2 * zx * zt;
        float hyt = d * zyt + hd2 * zy * zt;
        float hxxx = d * zxxx + hd2 * 3.0f * zx * zxx + c3 * zx * zx * zx;
        float hxxy = d * zxxy + hd2 * (zy * zxx + 2.0f * zx * zxy) + c3 * zx * zx * zy;
        float hxyy = d * zxyy + hd2 * (2.0f * zy * zxy + zx * zyy) + c3 * zx * zy * zy;
        float hyyy = d * zyyy + hd2 * 3.0f * zy * zyy + c3 * zy * zy * zy;

        float w0 = Wp2[kk];
        float w1 = Wp2[256 + kk];
        acc[0] += w0 * hx;   acc[1] += w0 * hy;   acc[2] += w0 * ht;
        acc[3] += w0 * hxx;  acc[4] += w0 * hxy;  acc[5] += w0 * hyy;
        acc[6] += w0 * hxt;  acc[7] += w0 * hyt;
        acc[8] += w0 * hxxx; acc[9] += w0 * hxxy;
        acc[10] += w0 * hxyy; acc[11] += w0 * hyyy;
        acc[12] += w1 * hx;  acc[13] += w1 * hy;
    }
#pragma unroll
    for (int i = 0; i < 14; i++)
#pragma unroll
        for (int o = 16; o; o >>= 1) acc[i] += __shfl_xor_sync(0xffffffffu, acc[i], o);

    if (lane == 0) {
        float lam1 = lam1p[0], lam2 = lam2p[0];
        float sx = acc[0], sy = acc[1];
        float sxx = acc[3], sxy = acc[4], syy = acc[5], sxt = acc[6], syt = acc[7];
        float sxxx = acc[8], sxxy = acc[9], sxyy = acc[10], syyy = acc[11];
        float px = acc[12], py = acc[13];
        float u = sy, v = -sx;
        float f = lam1 * (syt + u * sxy + v * syy) + px - lam2 * (sxxy + syyy);
        float g = lam1 * (-sxt + u * (-sxx) + v * (-sxy)) + py - lam2 * (-sxxx - sxyy);
        out[3 * NPTS + warp] = f;
        out[4 * NPTS + warp] = g;
    }
}

// ---------------------------------------------------------------------------
// Host launch
// ---------------------------------------------------------------------------
extern "C" void kernel_launch(void* const* d_in, const int* in_sizes, int n_in,
                              void* d_out, int out_size) {
    const float* x   = (const float*)d_in[0];
    const float* y   = (const float*)d_in[1];
    const float* t   = (const float*)d_in[2];
    const float* W1  = (const float*)d_in[6];
    const float* b1  = (const float*)d_in[7];
    const float* W2  = (const float*)d_in[8];
    const float* b2  = (const float*)d_in[9];
    const float* W3  = (const float*)d_in[10];
    const float* b3  = (const float*)d_in[11];
    const float* Wp1 = (const float*)d_in[12];
    const float* bp1 = (const float*)d_in[13];
    const float* Wp2 = (const float*)d_in[14];
    const float* Wd1 = (const float*)d_in[16];
    const float* bd1 = (const float*)d_in[17];
    const float* Wd2 = (const float*)d_in[18];
    const float* bd2 = (const float*)d_in[19];
    const float* lam1 = (const float*)d_in[20];
    const float* lam2 = (const float*)d_in[21];
    float* out = (float*)d_out;

    float *A = nullptr, *B = nullptr;
    cudaGetSymbolAddress((void**)&A, g_bufA);
    cudaGetSymbolAddress((void**)&B, g_bufB);

    const int NH = NPTS * HID;                     // 16,777,216
    const int M13_T = NCH * NPTS / 128;            // 6656
    const int M3_T  = 3 * NPTS / 128;              // 1536

    // Layer 1 + jet seed
    layer1_kernel<<<NH / 256, 256>>>(x, y, t, W1, b1, A);

    // Layer 2
    gemm_bf16<<<dim3(M13_T, 2), 256>>>(A, W2, B);
    combine_kernel<<<NH / 256, 256>>>(B, b2);

    // Layer 3
    gemm_bf16<<<dim3(M13_T, 2), 256>>>(B, W3, A);
    combine_kernel<<<NH / 256, 256>>>(A, b3);

    // Data head (channels 0..2 of A = first 3*N rows)
    gemm_bf16<<<dim3(M3_T, 2), 256>>>(A, Wd1, B);
    data_reduce<<<NPTS / 8, 256>>>(B, bd1, Wd2, bd2, out);

    // PDE head (all 13 channels)
    gemm_bf16<<<dim3(M13_T, 2), 256>>>(A, Wp1, B);
    pde_reduce<<<NPTS / 8, 256>>>(B, bp1, Wp2, lam1, lam2, out);
}

// round 3
// speedup vs baseline: 2.8542x; 1.3292x over previous
#include <cuda_runtime.h>
#include <cuda_bf16.h>

#define NPTS 65536
#define HID  256
#define SLICE ((size_t)NPTS * HID)
#define NCH  13

// fp32 GEMM-output buffer and bf16 hi/lo split activation buffers
static __device__ float          g_C  [(size_t)NCH * NPTS * HID];
static __device__ __nv_bfloat16  g_hiA[(size_t)NCH * NPTS * HID];
static __device__ __nv_bfloat16  g_loA[(size_t)NCH * NPTS * HID];
static __device__ __nv_bfloat16  g_hiB[(size_t)NCH * NPTS * HID];
static __device__ __nv_bfloat16  g_loB[(size_t)NCH * NPTS * HID];
// weight splits: slot 0=W2, 1=W3, 2=Wp1, 3=Wd1
static __device__ __nv_bfloat16  g_Whi[4 * 256 * 256];
static __device__ __nv_bfloat16  g_Wlo[4 * 256 * 256];

// ---------------------------------------------------------------------------
// hi = truncate-to-bf16(f), lo = RN-bf16(f - hi). Same numerics as R2 split2.
// ---------------------------------------------------------------------------
__device__ __forceinline__ void store_hl(__nv_bfloat16* __restrict__ hi,
                                         __nv_bfloat16* __restrict__ lo,
                                         size_t idx, float f) {
    unsigned u = __float_as_uint(f);
    float h = __uint_as_float(u & 0xFFFF0000u);
    hi[idx] = __ushort_as_bfloat16((unsigned short)(u >> 16));
    lo[idx] = __float2bfloat16(f - h);   // cvt.rn
}

// ---------------------------------------------------------------------------
// Weight split kernel: 4 matrices of 256x256
// ---------------------------------------------------------------------------
__global__ void wconv_kernel(const float* __restrict__ w2,
                             const float* __restrict__ w3,
                             const float* __restrict__ wp1,
                             const float* __restrict__ wd1) {
    int e = blockIdx.x * blockDim.x + threadIdx.x;   // 0 .. 4*65536-1
    if (e >= 4 * 65536) return;
    int m = e >> 16;
    int l = e & 65535;
    const float* src = (m == 0) ? w2 : (m == 1) ? w3 : (m == 2) ? wp1 : wd1;
    store_hl(g_Whi, g_Wlo, (size_t)e, src[l]);
}

// ---------------------------------------------------------------------------
// Layer 1: seed the 13-channel tanh jet, writing hi/lo bf16.
// ---------------------------------------------------------------------------
__global__ void layer1_kernel(const float* __restrict__ x,
                              const float* __restrict__ y,
                              const float* __restrict__ t,
                              const float* __restrict__ W1,
                              const float* __restrict__ b1) {
    int e = blockIdx.x * blockDim.x + threadIdx.x;
    if (e >= NPTS * HID) return;
    int n = e >> 8;
    int k = e & 255;
    float cx = W1[k * 3 + 0];
    float cy = W1[k * 3 + 1];
    float ct = W1[k * 3 + 2];
    float z = cx * x[n] + cy * y[n] + ct * t[n] + b1[k];
    float h = tanhf(z);
    float d = 1.0f - h * h;
    const size_t S = SLICE;
    store_hl(g_hiA, g_loA, e, h);
    store_hl(g_hiA, g_loA, S * 1 + e, d * cx);
    store_hl(g_hiA, g_loA, S * 2 + e, d * cy);
    store_hl(g_hiA, g_loA, S * 3 + e, d * ct);
    float m2 = -2.0f * h * d;
    store_hl(g_hiA, g_loA, S * 4 + e, m2 * cx * cx);
    store_hl(g_hiA, g_loA, S * 5 + e, m2 * cx * cy);
    store_hl(g_hiA, g_loA, S * 6 + e, m2 * cy * cy);
    store_hl(g_hiA, g_loA, S * 7 + e, m2 * cx * ct);
    store_hl(g_hiA, g_loA, S * 8 + e, m2 * cy * ct);
    float m3 = d * (6.0f * h * h - 2.0f);
    store_hl(g_hiA, g_loA, S * 9 + e,  m3 * cx * cx * cx);
    store_hl(g_hiA, g_loA, S * 10 + e, m3 * cx * cx * cy);
    store_hl(g_hiA, g_loA, S * 11 + e, m3 * cx * cy * cy);
    store_hl(g_hiA, g_loA, S * 12 + e, m3 * cy * cy * cy);
}

// ---------------------------------------------------------------------------
// Tensor-core GEMM (NT), C[m,n] = sum_k A[m,k]*W[n,k], K = N = 256.
// A,W pre-split into bf16 hi/lo. Block tile 128x128, 8 warps (32x64 warp tile),
// K-chunk 32, cp.async double-buffer, ldmatrix fragment loads.
// Accum: Ah*Wh + Ah*Wl + Al*Wh in fp32.
// smem layout per (stage, array): 128 rows x 80 bytes (64B data + 16B pad).
// ---------------------------------------------------------------------------
#define ROWB  80
#define ASTG  10240     // 128*80
#define SMSZ  (2*4*ASTG) // 81920

#define LDSM4(R, addr) \
    asm volatile("ldmatrix.sync.aligned.m8n8.x4.shared.b16 {%0,%1,%2,%3}, [%4];" \
                 : "=r"((R)[0]), "=r"((R)[1]), "=r"((R)[2]), "=r"((R)[3]) \
                 : "r"(addr))
#define CPA(dst, src) \
    asm volatile("cp.async.cg.shared.global [%0], [%1], 16;" :: "r"(dst), "l"(src))
#define CPC() asm volatile("cp.async.commit_group;")
#define CPW1() asm volatile("cp.async.wait_group 1;")
#define CPW0() asm volatile("cp.async.wait_group 0;")

__device__ __forceinline__ void mma_bf16(float* c, const unsigned* a,
                                         unsigned b0, unsigned b1) {
    asm volatile(
        "mma.sync.aligned.m16n8k16.row.col.f32.bf16.bf16.f32 "
        "{%0,%1,%2,%3}, {%4,%5,%6,%7}, {%8,%9}, {%0,%1,%2,%3};"
        : "+f"(c[0]), "+f"(c[1]), "+f"(c[2]), "+f"(c[3])
        : "r"(a[0]), "r"(a[1]), "r"(a[2]), "r"(a[3]), "r"(b0), "r"(b1));
}

__global__ void __launch_bounds__(256, 2)
gemm_v3(const __nv_bfloat16* __restrict__ Ahi,
        const __nv_bfloat16* __restrict__ Alo,
        const __nv_bfloat16* __restrict__ Whi,
        const __nv_bfloat16* __restrict__ Wlo,
        float* __restrict__ C) {
    extern __shared__ unsigned char sm[];
    const unsigned sb = (unsigned)__cvta_generic_to_shared(sm);

    const int tid  = threadIdx.x;
    const int lane = tid & 31;
    const int warp = tid >> 5;
    const int wm   = (warp & 3) * 32;
    const int wn   = (warp >> 2) * 64;

    const size_t blockRow = (size_t)blockIdx.x * 128;
    const int    blockN   = blockIdx.y * 128;

    // loader: each thread stages 2 consecutive 16B chunks per array
    const int lr = tid >> 1;          // row 0..127
    const int lc = (tid & 1) * 2;     // chunk base 0 or 2 (of 4 per 32-k row)
    const __nv_bfloat16* gAh = Ahi + (blockRow + lr) * 256;
    const __nv_bfloat16* gAl = Alo + (blockRow + lr) * 256;
    const __nv_bfloat16* gWh = Whi + (size_t)(blockN + lr) * 256;
    const __nv_bfloat16* gWl = Wlo + (size_t)(blockN + lr) * 256;
    const unsigned sdst = sb + lr * ROWB + lc * 16;

    float acc[2][8][4];
#pragma unroll
    for (int i = 0; i < 2; i++)
#pragma unroll
        for (int j = 0; j < 8; j++)
#pragma unroll
            for (int l = 0; l < 4; l++) acc[i][j][l] = 0.0f;

    // fragment address components
    const int arow = wm + (lane & 15);
    const int acsel = (lane >> 4);                 // 0/1 -> k half chunk
    const int brow = wn + (lane & 7) + ((lane >> 4) << 3);
    const int bcsel = (lane >> 3) & 1;

#define ISSUE(stage, kc) do {                                                  \
        int koff = (kc) * 32;                                                  \
        unsigned d0 = sdst + (stage) * (4 * ASTG);                             \
        CPA(d0 + 0 * ASTG,      gAh + koff + lc * 8);                          \
        CPA(d0 + 0 * ASTG + 16, gAh + koff + lc * 8 + 8);                      \
        CPA(d0 + 1 * ASTG,      gAl + koff + lc * 8);                          \
        CPA(d0 + 1 * ASTG + 16, gAl + koff + lc * 8 + 8);                      \
        CPA(d0 + 2 * ASTG,      gWh + koff + lc * 8);                          \
        CPA(d0 + 2 * ASTG + 16, gWh + koff + lc * 8 + 8);                      \
        CPA(d0 + 3 * ASTG,      gWl + koff + lc * 8);                          \
        CPA(d0 + 3 * ASTG + 16, gWl + koff + lc * 8 + 8);                      \
        CPC();                                                                 \
    } while (0)

    ISSUE(0, 0);

#pragma unroll 1
    for (int kc = 0; kc < 8; kc++) {
        if (kc < 7) ISSUE((kc + 1) & 1, kc + 1);
        if (kc < 7) { CPW1(); } else { CPW0(); }
        __syncthreads();

        const unsigned s0 = sb + (kc & 1) * (4 * ASTG);
#pragma unroll
        for (int step = 0; step < 2; step++) {
            unsigned aH[2][4], aL[2][4];
            const unsigned acol = (acsel + step * 2) * 16;
#pragma unroll
            for (int mt = 0; mt < 2; mt++) {
                LDSM4(aH[mt], s0 + 0 * ASTG + (arow + mt * 16) * ROWB + acol);
                LDSM4(aL[mt], s0 + 1 * ASTG + (arow + mt * 16) * ROWB + acol);
            }
            const unsigned bcol = (bcsel + step * 2) * 16;
#pragma unroll
            for (int ng = 0; ng < 4; ng++) {
                unsigned bh[4], bl[4];
                LDSM4(bh, s0 + 2 * ASTG + (brow + ng * 16) * ROWB + bcol);
                LDSM4(bl, s0 + 3 * ASTG + (brow + ng * 16) * ROWB + bcol);
#pragma unroll
                for (int mt = 0; mt < 2; mt++) {
                    mma_bf16(acc[mt][2 * ng],     aH[mt], bh[0], bh[1]);
                    mma_bf16(acc[mt][2 * ng],     aH[mt], bl[0], bl[1]);
                    mma_bf16(acc[mt][2 * ng],     aL[mt], bh[0], bh[1]);
                    mma_bf16(acc[mt][2 * ng + 1], aH[mt], bh[2], bh[3]);
                    mma_bf16(acc[mt][2 * ng + 1], aH[mt], bl[2], bl[3]);
                    mma_bf16(acc[mt][2 * ng + 1], aL[mt], bh[2], bh[3]);
                }
            }
        }
        __syncthreads();
    }

    // epilogue
    const int g  = lane >> 2;
    const int t4 = lane & 3;
#pragma unroll
    for (int mt = 0; mt < 2; mt++) {
        size_t row = blockRow + wm + mt * 16 + g;
#pragma unroll
        for (int nt = 0; nt < 8; nt++) {
            int col = blockN + wn + nt * 8 + t4 * 2;
            *(float2*)(C + row * 256 + col) =
                make_float2(acc[mt][nt][0], acc[mt][nt][1]);
            *(float2*)(C + (row + 8) * 256 + col) =
                make_float2(acc[mt][nt][2], acc[mt][nt][3]);
        }
    }
}

// ---------------------------------------------------------------------------
// Pointwise tanh jet propagation: reads fp32 Z (= g_C), writes hi/lo bf16.
// ---------------------------------------------------------------------------
__global__ void combine_kernel(const float* __restrict__ Z,
                               const float* __restrict__ b,
                               __nv_bfloat16* __restrict__ hi,
                               __nv_bfloat16* __restrict__ lo) {
    int e = blockIdx.x * blockDim.x + threadIdx.x;
    if (e >= NPTS * HID) return;
    int k = e & 255;
    const size_t S = SLICE;
    float zh = Z[e] + b[k];
    float zx = Z[S + e], zy = Z[2 * S + e], zt = Z[3 * S + e];
    float zxx = Z[4 * S + e], zxy = Z[5 * S + e], zyy = Z[6 * S + e];
    float zxt = Z[7 * S + e], zyt = Z[8 * S + e];
    float zxxx = Z[9 * S + e], zxxy = Z[10 * S + e];
    float zxyy = Z[11 * S + e], zyyy = Z[12 * S + e];

    float h = tanhf(zh);
    float d = 1.0f - h * h;
    float hd2 = -2.0f * h * d;
    float c3 = (4.0f * h * h - 2.0f * d) * d;

    store_hl(hi, lo, e, h);
    store_hl(hi, lo, S + e, d * zx);
    store_hl(hi, lo, 2 * S + e, d * zy);
    store_hl(hi, lo, 3 * S + e, d * zt);
    store_hl(hi, lo, 4 * S + e, d * zxx + hd2 * zx * zx);
    store_hl(hi, lo, 5 * S + e, d * zxy + hd2 * zx * zy);
    store_hl(hi, lo, 6 * S + e, d * zyy + hd2 * zy * zy);
    store_hl(hi, lo, 7 * S + e, d * zxt + hd2 * zx * zt);
    store_hl(hi, lo, 8 * S + e, d * zyt + hd2 * zy * zt);
    store_hl(hi, lo, 9 * S + e,  d * zxxx + hd2 * 3.0f * zx * zxx + c3 * zx * zx * zx);
    store_hl(hi, lo, 10 * S + e, d * zxxy + hd2 * (zy * zxx + 2.0f * zx * zxy) + c3 * zx * zx * zy);
    store_hl(hi, lo, 11 * S + e, d * zxyy + hd2 * (2.0f * zy * zxy + zx * zyy) + c3 * zx * zy * zy);
    store_hl(hi, lo, 12 * S + e, d * zyyy + hd2 * 3.0f * zy * zyy + c3 * zy * zy * zy);
}

// ---------------------------------------------------------------------------
// Data head reduction: one warp per sample.
// ---------------------------------------------------------------------------
__global__ void data_reduce(const float* __restrict__ Zd,
                            const float* __restrict__ bd1,
                            const float* __restrict__ Wd2,
                            const float* __restrict__ bd2,
                            float* __restrict__ out) {
    int warp = (blockIdx.x * blockDim.x + threadIdx.x) >> 5;
    int lane = threadIdx.x & 31;
    if (warp >= NPTS) return;
    const size_t S = SLICE;
    const size_t base = (size_t)warp * 256;
    float ap = 0.0f, au = 0.0f, av = 0.0f;
#pragma unroll
    for (int kk = lane; kk < 256; kk += 32) {
        size_t e = base + kk;
        float zh = Zd[e] + bd1[kk];
        float h = tanhf(zh);
        float d = 1.0f - h * h;
        float hx = d * Zd[S + e];
        float hy = d * Zd[2 * S + e];
        float w0 = Wd2[kk];
        float w1 = Wd2[256 + kk];
        ap += w1 * h;
        au += w0 * hy;
        av += w0 * hx;
    }
#pragma unroll
    for (int o = 16; o; o >>= 1) {
        ap += __shfl_xor_sync(0xffffffffu, ap, o);
        au += __shfl_xor_sync(0xffffffffu, au, o);
        av += __shfl_xor_sync(0xffffffffu, av, o);
    }
    if (lane == 0) {
        out[warp] = ap + bd2[1];
        out[NPTS + warp] = au;
        out[2 * NPTS + warp] = -av;
    }
}

// ---------------------------------------------------------------------------
// PDE head reduction: tanh jet + Wp2 contraction + NS residuals.
// ---------------------------------------------------------------------------
__global__ void pde_reduce(const float* __restrict__ Z,
                           const float* __restrict__ bp1,
                           const float* __restrict__ Wp2,
                           const float* __restrict__ lam1p,
                           const float* __restrict__ lam2p,
                           float* __restrict__ out) {
    int warp = (blockIdx.x * blockDim.x + threadIdx.x) >> 5;
    int lane = threadIdx.x & 31;
    if (warp >= NPTS) return;
    const size_t S = SLICE;
    const size_t base = (size_t)warp * 256;

    float acc[14];
#pragma unroll
    for (int i = 0; i < 14; i++) acc[i] = 0.0f;

#pragma unroll
    for (int kk = lane; kk < 256; kk += 32) {
        size_t e = base + kk;
        float zh = Z[e] + bp1[kk];
        float h = tanhf(zh);
        float d = 1.0f - h * h;
        float zx = Z[S + e], zy = Z[2 * S + e], zt = Z[3 * S + e];
        float zxx = Z[4 * S + e], zxy = Z[5 * S + e], zyy = Z[6 * S + e];
        float zxt = Z[7 * S + e], zyt = Z[8 * S + e];
        float zxxx = Z[9 * S + e], zxxy = Z[10 * S + e];
        float zxyy = Z[11 * S + e], zyyy = Z[12 * S + e];
        float hd2 = -2.0f * h * d;
        float c3 = (4.0f * h * h - 2.0f * d) * d;

        float hx = d * zx, hy = d * zy, ht = d * zt;
        float hxx = d * zxx + hd2 * zx * zx;
        float hxy = d * zxy + hd2 * zx * zy;
        float hyy = d * zyy + hd2 * zy * zy;
        float hxt = d * zxt + hd2 * zx * zt;
        float hyt = d * zyt + hd2 * zy * zt;
        float hxxx = d * zxxx + hd2 * 3.0f * zx * zxx + c3 * zx * zx * zx;
        float hxxy = d * zxxy + hd2 * (zy * zxx + 2.0f * zx * zxy) + c3 * zx * zx * zy;
        float hxyy = d * zxyy + hd2 * (2.0f * zy * zxy + zx * zyy) + c3 * zx * zy * zy;
        float hyyy = d * zyyy + hd2 * 3.0f * zy * zyy + c3 * zy * zy * zy;

        float w0 = Wp2[kk];
        float w1 = Wp2[256 + kk];
        acc[0] += w0 * hx;   acc[1] += w0 * hy;   acc[2] += w0 * ht;
        acc[3] += w0 * hxx;  acc[4] += w0 * hxy;  acc[5] += w0 * hyy;
        acc[6] += w0 * hxt;  acc[7] += w0 * hyt;
        acc[8] += w0 * hxxx; acc[9] += w0 * hxxy;
        acc[10] += w0 * hxyy; acc[11] += w0 * hyyy;
        acc[12] += w1 * hx;  acc[13] += w1 * hy;
    }
#pragma unroll
    for (int i = 0; i < 14; i++)
#pragma unroll
        for (int o = 16; o; o >>= 1) acc[i] += __shfl_xor_sync(0xffffffffu, acc[i], o);

    if (lane == 0) {
        float lam1 = lam1p[0], lam2 = lam2p[0];
        float sx = acc[0], sy = acc[1];
        float sxx = acc[3], sxy = acc[4], syy = acc[5], sxt = acc[6], syt = acc[7];
        float sxxx = acc[8], sxxy = acc[9], sxyy = acc[10], syyy = acc[11];
        float px = acc[12], py = acc[13];
        float u = sy, v = -sx;
        float f = lam1 * (syt + u * sxy + v * syy) + px - lam2 * (sxxy + syyy);
        float g = lam1 * (-sxt + u * (-sxx) + v * (-sxy)) + py - lam2 * (-sxxx - sxyy);
        out[3 * NPTS + warp] = f;
        out[4 * NPTS + warp] = g;
    }
}

// ---------------------------------------------------------------------------
// Host launch
// ---------------------------------------------------------------------------
extern "C" void kernel_launch(void* const* d_in, const int* in_sizes, int n_in,
                              void* d_out, int out_size) {
    const float* x   = (const float*)d_in[0];
    const float* y   = (const float*)d_in[1];
    const float* t   = (const float*)d_in[2];
    const float* W1  = (const float*)d_in[6];
    const float* b1  = (const float*)d_in[7];
    const float* W2  = (const float*)d_in[8];
    const float* b2  = (const float*)d_in[9];
    const float* W3  = (const float*)d_in[10];
    const float* b3  = (const float*)d_in[11];
    const float* Wp1 = (const float*)d_in[12];
    const float* bp1 = (const float*)d_in[13];
    const float* Wp2 = (const float*)d_in[14];
    const float* Wd1 = (const float*)d_in[16];
    const float* bd1 = (const float*)d_in[17];
    const float* Wd2 = (const float*)d_in[18];
    const float* bd2 = (const float*)d_in[19];
    const float* lam1 = (const float*)d_in[20];
    const float* lam2 = (const float*)d_in[21];
    float* out = (float*)d_out;

    float *C = nullptr;
    __nv_bfloat16 *hiA, *loA, *hiB, *loB, *Whi, *Wlo;
    cudaGetSymbolAddress((void**)&C,   g_C);
    cudaGetSymbolAddress((void**)&hiA, g_hiA);
    cudaGetSymbolAddress((void**)&loA, g_loA);
    cudaGetSymbolAddress((void**)&hiB, g_hiB);
    cudaGetSymbolAddress((void**)&loB, g_loB);
    cudaGetSymbolAddress((void**)&Whi, g_Whi);
    cudaGetSymbolAddress((void**)&Wlo, g_Wlo);

    static bool attr_set = false;
    if (!attr_set) {
        cudaFuncSetAttribute(gemm_v3, cudaFuncAttributeMaxDynamicSharedMemorySize, SMSZ);
        attr_set = true;
    }

    const int NH = NPTS * HID;
    const int M13_T = NCH * NPTS / 128;   // 6656
    const int M3_T  = 3 * NPTS / 128;     // 1536
    const int WOFF = 256 * 256;

    wconv_kernel<<<(4 * 65536) / 256, 256>>>(W2, W3, Wp1, Wd1);
    layer1_kernel<<<NH / 256, 256>>>(x, y, t, W1, b1);

    // Layer 2
    gemm_v3<<<dim3(M13_T, 2), 256, SMSZ>>>(hiA, loA, Whi + 0 * WOFF, Wlo + 0 * WOFF, C);
    combine_kernel<<<NH / 256, 256>>>(C, b2, hiB, loB);

    // Layer 3
    gemm_v3<<<dim3(M13_T, 2), 256, SMSZ>>>(hiB, loB, Whi + 1 * WOFF, Wlo + 1 * WOFF, C);
    combine_kernel<<<NH / 256, 256>>>(C, b3, hiA, loA);

    // Data head (first 3 channels of A)
    gemm_v3<<<dim3(M3_T, 2), 256, SMSZ>>>(hiA, loA, Whi + 3 * WOFF, Wlo + 3 * WOFF, C);
    data_reduce<<<NPTS / 8, 256>>>(C, bd1, Wd2, bd2, out);

    // PDE head (all 13 channels)
    gemm_v3<<<dim3(M13_T, 2), 256, SMSZ>>>(hiA, loA, Whi + 2 * WOFF, Wlo + 2 * WOFF, C);
    pde_reduce<<<NPTS / 8, 256>>>(C, bp1, Wp2, lam1, lam2, out);
}